// round 2
// baseline (speedup 1.0000x reference)
#include <cuda_runtime.h>
#include <cuda_bf16.h>
#include <math.h>

// Fixed shapes from reference setup_inputs
#define NB    32      // batch
#define NC    80      // classes
#define NG    128     // grid
#define NN    32      // boxes per batch (== warp size, exploited below)
#define GG    (NG*NG) // 16384
#define OBJ_TOTAL (NB*GG)   // 524288
#define DENSE_BLOCKS 256
#define GRID_BLOCKS (DENSE_BLOCKS + NB)   // 288
#define THREADS 256
#define FULL 0xffffffffu

// ---------------- persistent device scratch (zero-init at load; every launch
// leaves these zeroed again via read-and-reset in the finalize path) --------
// g_acc: 0: S1 = sum softplus(obj) over ALL cells
//        1: sum obj at masked cells
//        2: sum softplus(obj) at masked cells
//        3: raw coord sum (pre *5)
//        4: cls sparse correction sum
__device__ double g_acc[5];
__device__ int    g_Mtot;
__device__ int    g_done;

__device__ __forceinline__ float sp(float x) {
    // jax.nn.softplus(x) = max(x,0) + log1p(exp(-|x|))
    return fmaxf(x, 0.0f) + log1pf(expf(-fabsf(x)));
}

__device__ __forceinline__ double block_reduce(double v, double* sh) {
    int t = threadIdx.x;
    sh[t] = v;
    __syncthreads();
    #pragma unroll
    for (int s = THREADS / 2; s > 0; s >>= 1) {
        if (t < s) sh[t] += sh[t + s];
        __syncthreads();
    }
    double r = sh[0];
    __syncthreads();
    return r;
}

__device__ __forceinline__ double atomic_read_reset(double* p) {
    unsigned long long old = atomicExch((unsigned long long*)p, 0ull);
    return __longlong_as_double(old);
}

__global__ __launch_bounds__(THREADS)
void yolo_loss_fused_kernel(const float* __restrict__ cls_pred,
                            const float* __restrict__ reg_pred,
                            const float* __restrict__ obj_pred,
                            const int*   __restrict__ target_cls,
                            const float* __restrict__ target_box,
                            float* __restrict__ out) {
    __shared__ double sred[THREADS];
    __shared__ bool   is_last;
    // compact per-batch targets (built by warp 0 of each sparse block)
    __shared__ int          s_cell[NN];
    __shared__ float        s_reg[NN][4];
    __shared__ unsigned int s_bits[NN][3];
    __shared__ unsigned char s_msk[NN];
    __shared__ int          s_count;

    const int t   = threadIdx.x;
    const int bid = blockIdx.x;

    double a0 = 0.0;  // dense softplus(obj)
    double a1 = 0.0, a2 = 0.0, a3 = 0.0, a4 = 0.0;

    if (bid < DENSE_BLOCKS) {
        // ---------------- dense pass: sum softplus over all obj logits -------
        const float4* o4 = (const float4*)obj_pred;
        const int n4 = OBJ_TOTAL / 4;                       // 131072
        for (int i = bid * THREADS + t; i < n4; i += DENSE_BLOCKS * THREADS) {
            float4 v = o4[i];
            a0 += (double)(sp(v.x) + sp(v.y) + sp(v.z) + sp(v.w));
        }
        double r0 = block_reduce(a0, sred);
        if (t == 0 && r0 != 0.0) atomicAdd(&g_acc[0], r0);
    } else {
        // ---------------- sparse block: one batch's masked-cell corrections --
        const int b = bid - DENSE_BLOCKS;

        if (t < 32) {
            // warp 0: one lane per box; dedup cells with uniform shfl loop
            const float* box = target_box + ((size_t)b * NN + t) * 4;
            float x = box[0], y = box[1], w = box[2], h = box[3];
            int gx = (int)floorf(x * (float)NG);
            int gy = (int)floorf(y * (float)NG);
            int valid = (gx >= 0) && (gx < NG) && (gy >= 0) && (gy < NG);
            gx = min(max(gx, 0), NG - 1);
            gy = min(max(gy, 0), NG - 1);
            float one = valid ? 1.0f : 0.0f;
            int cell  = gy * NG + gx;
            float rv0 = (x * (float)NG - (float)gx) * one;
            float rv1 = (y * (float)NG - (float)gy) * one;
            float rv2 = sqrtf(w) * one;
            float rv3 = sqrtf(h) * one;
            int cl = target_cls[b * NN + t];

            // Aggregate over all lanes sharing my cell (ascending order ==
            // JAX .set last-write-wins for reg; OR for class bits; any-valid mask)
            float er0 = rv0, er1 = rv1, er2 = rv2, er3 = rv3;
            unsigned w0 = 0u, w1 = 0u, w2 = 0u;
            int anyvalid = 0;
            #pragma unroll
            for (int src = 0; src < 32; src++) {
                int   scell = __shfl_sync(FULL, cell, src);
                int   sval  = __shfl_sync(FULL, valid, src);
                int   scl   = __shfl_sync(FULL, cl, src);
                float s0 = __shfl_sync(FULL, rv0, src);
                float s1 = __shfl_sync(FULL, rv1, src);
                float s2 = __shfl_sync(FULL, rv2, src);
                float s3 = __shfl_sync(FULL, rv3, src);
                if (scell == cell) {
                    er0 = s0; er1 = s1; er2 = s2; er3 = s3;  // last write wins
                    if (sval) {
                        anyvalid = 1;
                        if      (scl < 32) w0 |= 1u << scl;
                        else if (scl < 64) w1 |= 1u << (scl - 32);
                        else               w2 |= 1u << (scl - 64);
                    }
                }
            }
            unsigned mmask  = __match_any_sync(FULL, cell);
            int      leader = (t == (__ffs(mmask) - 1));
            unsigned lb     = __ballot_sync(FULL, leader);
            if (leader) {
                int slot = __popc(lb & ((1u << t) - 1u));
                s_cell[slot]    = cell;
                s_reg[slot][0]  = er0; s_reg[slot][1] = er1;
                s_reg[slot][2]  = er2; s_reg[slot][3] = er3;
                s_bits[slot][0] = w0; s_bits[slot][1] = w1; s_bits[slot][2] = w2;
                s_msk[slot]     = (unsigned char)anyvalid;
            }
            if (t == 0) {
                s_count = __popc(lb);
                int m = 0;
                // masked count contribution (computed by lane 0 from ballot of
                // leaders with anyvalid) — do it simply below instead
            }
        }
        __syncthreads();

        // masked-cell count for this batch (thread 0)
        if (t == 0) {
            int m = 0;
            for (int e = 0; e < s_count; e++) m += s_msk[e];
            if (m) atomicAdd(&g_Mtot, m);
        }

        // per-entry corrections: t<80 -> cls channels, t in [80,84) -> reg, t==84 -> obj
        const int cnt = s_count;
        for (int e = 0; e < cnt; e++) {
            if (!s_msk[e]) continue;
            int cell = s_cell[e];
            if (t < NC) {
                float p  = __ldg(&cls_pred[((size_t)(b * NC + t)) * GG + cell]);
                float tt = ((s_bits[e][t >> 5] >> (t & 31)) & 1u) ? 1.0f : 0.0f;
                a4 += (double)(sp(p) - p * tt);
            } else if (t < NC + 4) {
                int c = t - NC;
                float d = __ldg(&reg_pred[((size_t)(b * 4 + c)) * GG + cell]) - s_reg[e][c];
                a3 += (double)(d * d);
            } else if (t == NC + 4) {
                float o = __ldg(&obj_pred[(size_t)b * GG + cell]);
                a1 += (double)o;
                a2 += (double)sp(o);
            }
        }

        double r1 = block_reduce(a1, sred);
        double r2 = block_reduce(a2, sred);
        double r3 = block_reduce(a3, sred);
        double r4 = block_reduce(a4, sred);
        if (t == 0) {
            if (r1 != 0.0) atomicAdd(&g_acc[1], r1);
            if (r2 != 0.0) atomicAdd(&g_acc[2], r2);
            if (r3 != 0.0) atomicAdd(&g_acc[3], r3);
            if (r4 != 0.0) atomicAdd(&g_acc[4], r4);
        }
    }

    // ---------------- finalize: last block computes outputs & resets state ---
    if (t == 0) {
        __threadfence();
        int old = atomicAdd(&g_done, 1);
        is_last = (old == GRID_BLOCKS - 1);
    }
    __syncthreads();

    if (is_last && t == 0) {
        const double LN2 = 0.6931471805599453;
        double S1   = atomic_read_reset(&g_acc[0]);
        double so   = atomic_read_reset(&g_acc[1]);
        double ssp  = atomic_read_reset(&g_acc[2]);
        double crd  = atomic_read_reset(&g_acc[3]);
        double clsS = atomic_read_reset(&g_acc[4]);
        double M    = (double)atomicExch(&g_Mtot, 0);
        atomicExch(&g_done, 0);

        double obj_loss   = S1 - so;
        double noobj_loss = 0.5 * (S1 - ssp + M * LN2);
        double coord_loss = 5.0 * crd;
        double cls_loss   = LN2 * (double)NC * ((double)OBJ_TOTAL - M) + clsS;
        double total      = obj_loss + noobj_loss + coord_loss + cls_loss;

        out[0] = (float)(total      / (double)NB);
        out[1] = (float)(obj_loss   / (double)NB);
        out[2] = (float)(noobj_loss / (double)NB);
        out[3] = (float)(coord_loss / (double)NB);
        out[4] = (float)(cls_loss   / (double)NB);
    }
}

extern "C" void kernel_launch(void* const* d_in, const int* in_sizes, int n_in,
                              void* d_out, int out_size) {
    const float* cls_pred   = (const float*)d_in[0];
    const float* reg_pred   = (const float*)d_in[1];
    const float* obj_pred   = (const float*)d_in[2];
    const int*   target_cls = (const int*)  d_in[3];
    const float* target_box = (const float*)d_in[4];
    float* out = (float*)d_out;

    yolo_loss_fused_kernel<<<GRID_BLOCKS, THREADS>>>(
        cls_pred, reg_pred, obj_pred, target_cls, target_box, out);
}

// round 5
// speedup vs baseline: 1.6383x; 1.6383x over previous
#include <cuda_runtime.h>
#include <cuda_bf16.h>
#include <math.h>

// Fixed shapes from reference setup_inputs
#define NB    32      // batch
#define NC    80      // classes
#define NG    128     // grid
#define NN    32      // boxes per batch (== warp size)
#define GG    (NG*NG) // 16384
#define OBJ_TOTAL (NB*GG)   // 524288
#define DENSE_BLOCKS 128
#define GRID_BLOCKS (DENSE_BLOCKS + NB)   // 160; sparse blocks are bid<NB
#define THREADS 256
#define NWARPS (THREADS/32)
#define FULL 0xffffffffu

// ---------------- persistent device scratch (zero-init at load; every launch
// leaves these zeroed again via read-and-reset in the finalize path) --------
// g_acc: 0: S1 = sum softplus(obj) over ALL cells
//        1: sum obj at masked cells
//        2: sum softplus(obj) at masked cells
//        3: raw coord sum (pre *5)
//        4: cls sparse correction sum
__device__ double g_acc[5];
__device__ int    g_Mtot;
__device__ int    g_done;

__device__ __forceinline__ float sp(float x) {
    // jax.nn.softplus(x) = max(x,0) + log1p(exp(-|x|))
    return fmaxf(x, 0.0f) + log1pf(__expf(-fabsf(x)));
}

__device__ __forceinline__ float warp_sum(float v) {
    #pragma unroll
    for (int o = 16; o; o >>= 1) v += __shfl_xor_sync(FULL, v, o);
    return v;
}

__device__ __forceinline__ double atomic_read_reset(double* p) {
    unsigned long long old = atomicExch((unsigned long long*)p, 0ull);
    return __longlong_as_double(old);
}

__global__ __launch_bounds__(THREADS)
void yolo_loss_fused_kernel(const float* __restrict__ cls_pred,
                            const float* __restrict__ reg_pred,
                            const float* __restrict__ obj_pred,
                            const int*   __restrict__ target_cls,
                            const float* __restrict__ target_box,
                            float* __restrict__ out) {
    __shared__ bool   is_last;
    __shared__ float  swsum[NWARPS][4];     // per-warp partials (up to 4 accums)
    // compact per-batch MASKED targets (built by warp 0 of each sparse block)
    __shared__ int          s_cell[NN];
    __shared__ float        s_reg[NN][4];
    __shared__ unsigned int s_bits[NN][3];
    __shared__ int          s_count;        // number of masked (valid) cells

    const int t    = threadIdx.x;
    const int bid  = blockIdx.x;
    const int wid  = t >> 5;
    const int lane = t & 31;

    if (bid >= NB) {
        // ---------------- dense pass: sum softplus over all obj logits -------
        // 131072 float4 / (128 blocks * 256 thr) = 4 independent loads/thread
        const int did = bid - NB;
        float a0 = 0.0f;
        const float4* o4 = (const float4*)obj_pred;
        const int n4 = OBJ_TOTAL / 4;
        #pragma unroll 4
        for (int i = did * THREADS + t; i < n4; i += DENSE_BLOCKS * THREADS) {
            float4 v = o4[i];
            a0 += sp(v.x) + sp(v.y) + sp(v.z) + sp(v.w);
        }
        float w0 = warp_sum(a0);
        if (lane == 0) swsum[wid][0] = w0;
        __syncthreads();
        if (t == 0) {
            double r0 = 0.0;
            #pragma unroll
            for (int i = 0; i < NWARPS; i++) r0 += (double)swsum[i][0];
            if (r0 != 0.0) atomicAdd(&g_acc[0], r0);
        }
    } else {
        // ---------------- sparse block: one batch's masked-cell corrections --
        const int b = bid;

        if (t < 32) {
            // one lane per box; dedup cells via uniform shfl loop
            const float* box = target_box + ((size_t)b * NN + t) * 4;
            float x = box[0], y = box[1], w = box[2], h = box[3];
            int gx = (int)floorf(x * (float)NG);
            int gy = (int)floorf(y * (float)NG);
            int valid = (gx >= 0) && (gx < NG) && (gy >= 0) && (gy < NG);
            gx = min(max(gx, 0), NG - 1);
            gy = min(max(gy, 0), NG - 1);
            float one = valid ? 1.0f : 0.0f;
            int cell  = gy * NG + gx;
            float rv0 = (x * (float)NG - (float)gx) * one;
            float rv1 = (y * (float)NG - (float)gy) * one;
            float rv2 = sqrtf(w) * one;
            float rv3 = sqrtf(h) * one;
            int cl = target_cls[b * NN + t];

            // aggregate over lanes sharing my cell: ascending src order ==
            // JAX .set last-write-wins for reg; OR for class bits; any-valid
            float er0 = rv0, er1 = rv1, er2 = rv2, er3 = rv3;
            unsigned bw0 = 0u, bw1 = 0u, bw2 = 0u;
            int anyvalid = 0;
            #pragma unroll
            for (int src = 0; src < 32; src++) {
                int   scell = __shfl_sync(FULL, cell, src);
                int   sval  = __shfl_sync(FULL, valid, src);
                int   scl   = __shfl_sync(FULL, cl, src);
                float s0 = __shfl_sync(FULL, rv0, src);
                float s1 = __shfl_sync(FULL, rv1, src);
                float s2 = __shfl_sync(FULL, rv2, src);
                float s3 = __shfl_sync(FULL, rv3, src);
                if (scell == cell) {
                    er0 = s0; er1 = s1; er2 = s2; er3 = s3;  // last write wins
                    if (sval) {
                        anyvalid = 1;
                        if      (scl < 32) bw0 |= 1u << scl;
                        else if (scl < 64) bw1 |= 1u << (scl - 32);
                        else               bw2 |= 1u << (scl - 64);
                    }
                }
            }
            unsigned mmask  = __match_any_sync(FULL, cell);
            int      leader = (t == (__ffs(mmask) - 1));
            // only MASKED (anyvalid) leader entries are stored; unmasked cells
            // contribute nothing to any loss term.
            unsigned mv = __ballot_sync(FULL, leader && anyvalid);
            if (leader && anyvalid) {
                int slot = __popc(mv & ((1u << t) - 1u));
                s_cell[slot]    = cell;
                s_reg[slot][0]  = er0; s_reg[slot][1] = er1;
                s_reg[slot][2]  = er2; s_reg[slot][3] = er3;
                s_bits[slot][0] = bw0; s_bits[slot][1] = bw1; s_bits[slot][2] = bw2;
            }
            if (t == 0) {
                int m = __popc(mv);
                s_count = m;
                if (m) atomicAdd(&g_Mtot, m);
            }
        }
        __syncthreads();

        // flattened (entry, channel) index space: every thread issues many
        // INDEPENDENT scattered loads -> high MLP instead of a serial chain.
        // c: 0..79 cls channels, 80..83 reg, 84 obj, 85..127 idle pad.
        float a1 = 0.0f, a2 = 0.0f, a3 = 0.0f, a4 = 0.0f;
        const int total = s_count << 7;      // s_count * 128
        for (int idx = t; idx < total; idx += THREADS) {
            const int e = idx >> 7;
            const int c = idx & 127;
            const int cell = s_cell[e];
            if (c < NC) {
                float p  = __ldg(&cls_pred[((size_t)(b * NC + c)) * GG + cell]);
                float tt = ((s_bits[e][c >> 5] >> (c & 31)) & 1u) ? 1.0f : 0.0f;
                a4 += sp(p) - p * tt;
            } else if (c < NC + 4) {
                const int r = c - NC;
                float d = __ldg(&reg_pred[((size_t)(b * 4 + r)) * GG + cell]) - s_reg[e][r];
                a3 += d * d;
            } else if (c == NC + 4) {
                float o = __ldg(&obj_pred[(size_t)b * GG + cell]);
                a1 += o;
                a2 += sp(o);
            }
        }

        float w1 = warp_sum(a1), w2 = warp_sum(a2), w3 = warp_sum(a3), w4 = warp_sum(a4);
        if (lane == 0) {
            swsum[wid][0] = w1; swsum[wid][1] = w2;
            swsum[wid][2] = w3; swsum[wid][3] = w4;
        }
        __syncthreads();
        if (t == 0) {
            double r1 = 0.0, r2 = 0.0, r3 = 0.0, r4 = 0.0;
            #pragma unroll
            for (int i = 0; i < NWARPS; i++) {
                r1 += (double)swsum[i][0]; r2 += (double)swsum[i][1];
                r3 += (double)swsum[i][2]; r4 += (double)swsum[i][3];
            }
            if (r1 != 0.0) atomicAdd(&g_acc[1], r1);
            if (r2 != 0.0) atomicAdd(&g_acc[2], r2);
            if (r3 != 0.0) atomicAdd(&g_acc[3], r3);
            if (r4 != 0.0) atomicAdd(&g_acc[4], r4);
        }
    }

    // ---------------- finalize: last block computes outputs & resets state ---
    if (t == 0) {
        __threadfence();
        int old = atomicAdd(&g_done, 1);
        is_last = (old == GRID_BLOCKS - 1);
    }
    __syncthreads();

    if (is_last && t == 0) {
        const double LN2 = 0.6931471805599453;
        double S1   = atomic_read_reset(&g_acc[0]);
        double so   = atomic_read_reset(&g_acc[1]);
        double ssp  = atomic_read_reset(&g_acc[2]);
        double crd  = atomic_read_reset(&g_acc[3]);
        double clsS = atomic_read_reset(&g_acc[4]);
        double M    = (double)atomicExch(&g_Mtot, 0);
        atomicExch(&g_done, 0);

        double obj_loss   = S1 - so;
        double noobj_loss = 0.5 * (S1 - ssp + M * LN2);
        double coord_loss = 5.0 * crd;
        double cls_loss   = LN2 * (double)NC * ((double)OBJ_TOTAL - M) + clsS;
        double total      = obj_loss + noobj_loss + coord_loss + cls_loss;

        out[0] = (float)(total      / (double)NB);
        out[1] = (float)(obj_loss   / (double)NB);
        out[2] = (float)(noobj_loss / (double)NB);
        out[3] = (float)(coord_loss / (double)NB);
        out[4] = (float)(cls_loss   / (double)NB);
    }
}

extern "C" void kernel_launch(void* const* d_in, const int* in_sizes, int n_in,
                              void* d_out, int out_size) {
    const float* cls_pred   = (const float*)d_in[0];
    const float* reg_pred   = (const float*)d_in[1];
    const float* obj_pred   = (const float*)d_in[2];
    const int*   target_cls = (const int*)  d_in[3];
    const float* target_box = (const float*)d_in[4];
    float* out = (float*)d_out;

    yolo_loss_fused_kernel<<<GRID_BLOCKS, THREADS>>>(
        cls_pred, reg_pred, obj_pred, target_cls, target_box, out);
}

// round 6
// speedup vs baseline: 2.2515x; 1.3743x over previous
#include <cuda_runtime.h>
#include <cuda_bf16.h>
#include <math.h>

// Fixed shapes from reference setup_inputs
#define NB    32      // batch
#define NC    80      // classes
#define NG    128     // grid
#define NN    32      // boxes per batch (== warp size)
#define GG    (NG*NG) // 16384
#define OBJ_TOTAL (NB*GG)   // 524288
#define DENSE_BLOCKS 256
#define GRID_BLOCKS (DENSE_BLOCKS + NB)   // 288; sparse blocks are bid<NB
#define THREADS 256
#define NWARPS (THREADS/32)
#define SPARSE_ITERS 16     // 32 entries * 128 channel-slots / 256 threads
#define FULL 0xffffffffu

// ---------------- persistent device scratch (zero-init at load; every launch
// leaves these zeroed again via read-and-reset in the finalize path) --------
__device__ double g_acc[5];   // 0:S1  1:sum obj@mask  2:sum sp(obj)@mask  3:coord raw  4:cls sparse
__device__ int    g_Mtot;
__device__ int    g_done;

__device__ __forceinline__ float sp(float x) {
    // jax.nn.softplus(x) = max(x,0) + log1p(exp(-|x|))
    return fmaxf(x, 0.0f) + log1pf(__expf(-fabsf(x)));
}

__device__ __forceinline__ float warp_sum(float v) {
    #pragma unroll
    for (int o = 16; o; o >>= 1) v += __shfl_xor_sync(FULL, v, o);
    return v;
}

__device__ __forceinline__ double atomic_read_reset(double* p) {
    unsigned long long old = atomicExch((unsigned long long*)p, 0ull);
    return __longlong_as_double(old);
}

__global__ __launch_bounds__(THREADS)
void yolo_loss_fused_kernel(const float* __restrict__ cls_pred,
                            const float* __restrict__ reg_pred,
                            const float* __restrict__ obj_pred,
                            const int*   __restrict__ target_cls,
                            const float* __restrict__ target_box,
                            float* __restrict__ out) {
    __shared__ bool   is_last;
    __shared__ float  swsum[NWARPS][4];
    // compact per-batch MASKED targets (built by warp 0 of each sparse block)
    __shared__ int          s_cell[NN];
    __shared__ float        s_reg[NN][4];
    __shared__ unsigned int s_bits[NN][3];
    __shared__ int          s_count;

    const int t    = threadIdx.x;
    const int bid  = blockIdx.x;
    const int wid  = t >> 5;
    const int lane = t & 31;

    if (bid >= NB) {
        // ---------------- dense pass: sum softplus over all obj logits -------
        // 131072 float4 / (256 blocks * 256 thr) = exactly 2 loads/thread,
        // fully unrolled -> both LDG.128 in flight before any use.
        const int did = bid - NB;
        const float4* o4 = (const float4*)obj_pred;
        const int base = did * THREADS + t;
        float4 v0 = o4[base];
        float4 v1 = o4[base + DENSE_BLOCKS * THREADS];
        float a0 = sp(v0.x) + sp(v0.y) + sp(v0.z) + sp(v0.w)
                 + sp(v1.x) + sp(v1.y) + sp(v1.z) + sp(v1.w);
        float w0 = warp_sum(a0);
        if (lane == 0) swsum[wid][0] = w0;
        __syncthreads();
        if (t == 0) {
            double r0 = 0.0;
            #pragma unroll
            for (int i = 0; i < NWARPS; i++) r0 += (double)swsum[i][0];
            if (r0 != 0.0) atomicAdd(&g_acc[0], r0);
        }
    } else {
        // ---------------- sparse block: one batch's masked-cell corrections --
        const int b = bid;

        if (t < 32) {
            // one lane per box; dedup cells via uniform shfl loop
            const float* box = target_box + ((size_t)b * NN + t) * 4;
            float x = box[0], y = box[1], w = box[2], h = box[3];
            int gx = (int)floorf(x * (float)NG);
            int gy = (int)floorf(y * (float)NG);
            int valid = (gx >= 0) && (gx < NG) && (gy >= 0) && (gy < NG);
            gx = min(max(gx, 0), NG - 1);
            gy = min(max(gy, 0), NG - 1);
            float one = valid ? 1.0f : 0.0f;
            int cell  = gy * NG + gx;
            float rv0 = (x * (float)NG - (float)gx) * one;
            float rv1 = (y * (float)NG - (float)gy) * one;
            float rv2 = sqrtf(w) * one;
            float rv3 = sqrtf(h) * one;
            int cl = target_cls[b * NN + t];

            // aggregate over lanes sharing my cell: ascending src order ==
            // JAX .set last-write-wins for reg; OR for class bits; any-valid
            float er0 = rv0, er1 = rv1, er2 = rv2, er3 = rv3;
            unsigned bw0 = 0u, bw1 = 0u, bw2 = 0u;
            int anyvalid = 0;
            #pragma unroll
            for (int src = 0; src < 32; src++) {
                int   scell = __shfl_sync(FULL, cell, src);
                int   sval  = __shfl_sync(FULL, valid, src);
                int   scl   = __shfl_sync(FULL, cl, src);
                float s0 = __shfl_sync(FULL, rv0, src);
                float s1 = __shfl_sync(FULL, rv1, src);
                float s2 = __shfl_sync(FULL, rv2, src);
                float s3 = __shfl_sync(FULL, rv3, src);
                if (scell == cell) {
                    er0 = s0; er1 = s1; er2 = s2; er3 = s3;  // last write wins
                    if (sval) {
                        anyvalid = 1;
                        if      (scl < 32) bw0 |= 1u << scl;
                        else if (scl < 64) bw1 |= 1u << (scl - 32);
                        else               bw2 |= 1u << (scl - 64);
                    }
                }
            }
            unsigned mmask  = __match_any_sync(FULL, cell);
            int      leader = (t == (__ffs(mmask) - 1));
            unsigned mv = __ballot_sync(FULL, leader && anyvalid);
            if (leader && anyvalid) {
                int slot = __popc(mv & ((1u << t) - 1u));
                s_cell[slot]    = cell;
                s_reg[slot][0]  = er0; s_reg[slot][1] = er1;
                s_reg[slot][2]  = er2; s_reg[slot][3] = er3;
                s_bits[slot][0] = bw0; s_bits[slot][1] = bw1; s_bits[slot][2] = bw2;
            }
            if (t == 0) {
                int m = __popc(mv);
                s_count = m;
                if (m) atomicAdd(&g_Mtot, m);
            }
        }
        __syncthreads();

        float a1 = 0.0f, a2 = 0.0f, a3 = 0.0f, a4 = 0.0f;
        const int cnt = s_count;             // uniform across block
        if (cnt > 0) {
            // Fixed 32-entry padded index space (entry e, channel c):
            //   idx = e*128 + c; c: 0..79 cls, 80..83 reg, 84 obj, 85..127 pad.
            // Padded entries (e >= cnt) alias slot 0's cell (valid address)
            // with weight 0. Phase 1 issues ONE unified LDG per iteration with
            // a compile-time trip count -> 16 front-batched loads (MLP=16).
            float vv[SPARSE_ITERS];
            #pragma unroll
            for (int k = 0; k < SPARSE_ITERS; k++) {
                const int idx  = t + k * THREADS;
                const int e    = idx >> 7;
                const int c    = idx & 127;
                const int es   = (e < cnt) ? e : 0;
                const int cell = s_cell[es];
                const float* p;
                if (c < NC)          p = cls_pred + ((size_t)(b * NC + c)) * GG + cell;
                else if (c < NC + 4) p = reg_pred + ((size_t)(b * 4 + (c - NC))) * GG + cell;
                else                 p = obj_pred + (size_t)b * GG + cell;
                vv[k] = __ldg(p);
            }
            #pragma unroll
            for (int k = 0; k < SPARSE_ITERS; k++) {
                const int idx = t + k * THREADS;
                const int e   = idx >> 7;
                const int c   = idx & 127;
                const int es  = (e < cnt) ? e : 0;
                const float w = (e < cnt) ? 1.0f : 0.0f;
                const float v = vv[k];
                if (c < NC) {
                    float tt = ((s_bits[es][c >> 5] >> (c & 31)) & 1u) ? 1.0f : 0.0f;
                    a4 += w * (sp(v) - v * tt);
                } else if (c < NC + 4) {
                    float d = v - s_reg[es][c - NC];
                    a3 += w * d * d;
                } else if (c == NC + 4) {
                    a1 += w * v;
                    a2 += w * sp(v);
                }
            }
        }

        float w1 = warp_sum(a1), w2 = warp_sum(a2), w3 = warp_sum(a3), w4 = warp_sum(a4);
        if (lane == 0) {
            swsum[wid][0] = w1; swsum[wid][1] = w2;
            swsum[wid][2] = w3; swsum[wid][3] = w4;
        }
        __syncthreads();
        if (t == 0) {
            double r1 = 0.0, r2 = 0.0, r3 = 0.0, r4 = 0.0;
            #pragma unroll
            for (int i = 0; i < NWARPS; i++) {
                r1 += (double)swsum[i][0]; r2 += (double)swsum[i][1];
                r3 += (double)swsum[i][2]; r4 += (double)swsum[i][3];
            }
            if (r1 != 0.0) atomicAdd(&g_acc[1], r1);
            if (r2 != 0.0) atomicAdd(&g_acc[2], r2);
            if (r3 != 0.0) atomicAdd(&g_acc[3], r3);
            if (r4 != 0.0) atomicAdd(&g_acc[4], r4);
        }
    }

    // ---------------- finalize: last block computes outputs & resets state ---
    if (t == 0) {
        __threadfence();
        int old = atomicAdd(&g_done, 1);
        is_last = (old == GRID_BLOCKS - 1);
    }
    __syncthreads();

    if (is_last && t == 0) {
        const double LN2 = 0.6931471805599453;
        double S1   = atomic_read_reset(&g_acc[0]);
        double so   = atomic_read_reset(&g_acc[1]);
        double ssp  = atomic_read_reset(&g_acc[2]);
        double crd  = atomic_read_reset(&g_acc[3]);
        double clsS = atomic_read_reset(&g_acc[4]);
        double M    = (double)atomicExch(&g_Mtot, 0);
        atomicExch(&g_done, 0);

        double obj_loss   = S1 - so;
        double noobj_loss = 0.5 * (S1 - ssp + M * LN2);
        double coord_loss = 5.0 * crd;
        double cls_loss   = LN2 * (double)NC * ((double)OBJ_TOTAL - M) + clsS;
        double total      = obj_loss + noobj_loss + coord_loss + cls_loss;

        out[0] = (float)(total      / (double)NB);
        out[1] = (float)(obj_loss   / (double)NB);
        out[2] = (float)(noobj_loss / (double)NB);
        out[3] = (float)(coord_loss / (double)NB);
        out[4] = (float)(cls_loss   / (double)NB);
    }
}

extern "C" void kernel_launch(void* const* d_in, const int* in_sizes, int n_in,
                              void* d_out, int out_size) {
    const float* cls_pred   = (const float*)d_in[0];
    const float* reg_pred   = (const float*)d_in[1];
    const float* obj_pred   = (const float*)d_in[2];
    const int*   target_cls = (const int*)  d_in[3];
    const float* target_box = (const float*)d_in[4];
    float* out = (float*)d_out;

    yolo_loss_fused_kernel<<<GRID_BLOCKS, THREADS>>>(
        cls_pred, reg_pred, obj_pred, target_cls, target_box, out);
}

// round 8
// speedup vs baseline: 3.0078x; 1.3359x over previous
#include <cuda_runtime.h>
#include <cuda_bf16.h>
#include <math.h>

// Fixed shapes from reference setup_inputs
#define NB    32      // batch
#define NC    80      // classes
#define NG    128     // grid
#define NN    32      // boxes per batch (== warp size)
#define GG    (NG*NG) // 16384
#define OBJ_TOTAL (NB*GG)   // 524288
#define SPARSE_SPLIT 4                    // blocks per batch for the gather
#define SPARSE_BLOCKS (NB * SPARSE_SPLIT) // 128
#define ENTRIES_PER_SPLIT (NN / SPARSE_SPLIT) // 8
#define DENSE_BLOCKS 256
#define GRID_BLOCKS (SPARSE_BLOCKS + DENSE_BLOCKS)  // 384
#define THREADS 256
#define NWARPS (THREADS/32)
#define NCH 85                 // 80 cls + 4 reg + 1 obj channels per entry
#define SPARSE_ITERS 3         // ceil(8*85/256) = ceil(680/256)
#define FULL 0xffffffffu

// ---------------- persistent device scratch (zero-init at load; every launch
// leaves these zeroed again via read-and-reset in the finalize path) --------
__device__ double g_acc[5];   // 0:S1  1:sum obj@mask  2:sum sp(obj)@mask  3:coord raw  4:cls sparse
__device__ int    g_Mtot;
__device__ int    g_done;

// MUFU ex2/lg2 via inline PTX (toolchain-independent device intrinsics)
__device__ __forceinline__ float ex2f(float x) {
    float r;
    asm("ex2.approx.f32 %0, %1;" : "=f"(r) : "f"(x));
    return r;
}
__device__ __forceinline__ float lg2f(float x) {
    float r;
    asm("lg2.approx.f32 %0, %1;" : "=f"(r) : "f"(x));
    return r;
}

__device__ __forceinline__ float sp(float x) {
    // softplus via MUFU only: max(x,0) + ln2*log2(1 + 2^(-|x|*log2e))
    float e = ex2f(fabsf(x) * -1.4426950408889634f);
    return fmaxf(x, 0.0f) + 0.6931471805599453f * lg2f(1.0f + e);
}

__device__ __forceinline__ float warp_sum(float v) {
    #pragma unroll
    for (int o = 16; o; o >>= 1) v += __shfl_xor_sync(FULL, v, o);
    return v;
}

__device__ __forceinline__ double atomic_read_reset(double* p) {
    unsigned long long old = atomicExch((unsigned long long*)p, 0ull);
    return __longlong_as_double(old);
}

__global__ __launch_bounds__(THREADS)
void yolo_loss_fused_kernel(const float* __restrict__ cls_pred,
                            const float* __restrict__ reg_pred,
                            const float* __restrict__ obj_pred,
                            const int*   __restrict__ target_cls,
                            const float* __restrict__ target_box,
                            float* __restrict__ out) {
    __shared__ bool   is_last;
    __shared__ float  swsum[NWARPS][4];
    // compact per-batch MASKED targets (rebuilt identically by each split block)
    __shared__ int          s_cell[NN];
    __shared__ float        s_reg[NN][4];
    __shared__ unsigned int s_bits[NN][3];
    __shared__ int          s_count;

    const int t    = threadIdx.x;
    const int bid  = blockIdx.x;
    const int wid  = t >> 5;
    const int lane = t & 31;

    if (bid >= SPARSE_BLOCKS) {
        // ---------------- dense pass: sum softplus over all obj logits -------
        // 131072 float4 / (256 blocks * 256 thr) = exactly 2 loads/thread.
        const int did = bid - SPARSE_BLOCKS;
        const float4* o4 = (const float4*)obj_pred;
        const int base = did * THREADS + t;
        float4 v0 = o4[base];
        float4 v1 = o4[base + DENSE_BLOCKS * THREADS];
        float a0 = sp(v0.x) + sp(v0.y) + sp(v0.z) + sp(v0.w)
                 + sp(v1.x) + sp(v1.y) + sp(v1.z) + sp(v1.w);
        float w0 = warp_sum(a0);
        if (lane == 0) swsum[wid][0] = w0;
        __syncthreads();
        if (t == 0) {
            double r0 = 0.0;
            #pragma unroll
            for (int i = 0; i < NWARPS; i++) r0 += (double)swsum[i][0];
            if (r0 != 0.0) atomicAdd(&g_acc[0], r0);
        }
    } else {
        // ------- sparse block: slice r of batch b's masked-cell corrections --
        const int b = bid >> 2;          // bid / SPARSE_SPLIT
        const int r = bid & 3;           // slice index 0..3

        if (t < 32) {
            // one lane per box; dedup cells via uniform shfl loop (identical
            // and deterministic across the 4 split blocks of this batch)
            const float* box = target_box + ((size_t)b * NN + t) * 4;
            float x = box[0], y = box[1], w = box[2], h = box[3];
            int gx = (int)floorf(x * (float)NG);
            int gy = (int)floorf(y * (float)NG);
            int valid = (gx >= 0) && (gx < NG) && (gy >= 0) && (gy < NG);
            gx = min(max(gx, 0), NG - 1);
            gy = min(max(gy, 0), NG - 1);
            float one = valid ? 1.0f : 0.0f;
            int cell  = gy * NG + gx;
            float rv0 = (x * (float)NG - (float)gx) * one;
            float rv1 = (y * (float)NG - (float)gy) * one;
            float rv2 = sqrtf(w) * one;
            float rv3 = sqrtf(h) * one;
            int cl = target_cls[b * NN + t];

            // ascending src order == JAX .set last-write-wins for reg;
            // OR for class bits; any-valid for mask
            float er0 = rv0, er1 = rv1, er2 = rv2, er3 = rv3;
            unsigned bw0 = 0u, bw1 = 0u, bw2 = 0u;
            int anyvalid = 0;
            #pragma unroll
            for (int src = 0; src < 32; src++) {
                int   scell = __shfl_sync(FULL, cell, src);
                int   sval  = __shfl_sync(FULL, valid, src);
                int   scl   = __shfl_sync(FULL, cl, src);
                float s0 = __shfl_sync(FULL, rv0, src);
                float s1 = __shfl_sync(FULL, rv1, src);
                float s2 = __shfl_sync(FULL, rv2, src);
                float s3 = __shfl_sync(FULL, rv3, src);
                if (scell == cell) {
                    er0 = s0; er1 = s1; er2 = s2; er3 = s3;  // last write wins
                    if (sval) {
                        anyvalid = 1;
                        if      (scl < 32) bw0 |= 1u << scl;
                        else if (scl < 64) bw1 |= 1u << (scl - 32);
                        else               bw2 |= 1u << (scl - 64);
                    }
                }
            }
            unsigned mmask  = __match_any_sync(FULL, cell);
            int      leader = (t == (__ffs(mmask) - 1));
            unsigned mv = __ballot_sync(FULL, leader && anyvalid);
            if (leader && anyvalid) {
                int slot = __popc(mv & ((1u << t) - 1u));
                s_cell[slot]    = cell;
                s_reg[slot][0]  = er0; s_reg[slot][1] = er1;
                s_reg[slot][2]  = er2; s_reg[slot][3] = er3;
                s_bits[slot][0] = bw0; s_bits[slot][1] = bw1; s_bits[slot][2] = bw2;
            }
            if (t == 0) {
                int m = __popc(mv);
                s_count = m;
                if (m && r == 0) atomicAdd(&g_Mtot, m);  // count once per batch
            }
        }
        __syncthreads();

        float a1 = 0.0f, a2 = 0.0f, a3 = 0.0f, a4 = 0.0f;
        const int cnt = s_count;             // uniform across block
        if (cnt > 0) {
            // This block handles entries [r*8, r*8+8); 85 channels per entry
            // (0..79 cls, 80..83 reg, 84 obj). 680 slots over 3x256 threads;
            // out-of-range slots alias entry slot 0 with weight 0.
            float vv[SPARSE_ITERS];
            int   ee[SPARSE_ITERS], cc[SPARSE_ITERS];
            float ww[SPARSE_ITERS];
            #pragma unroll
            for (int k = 0; k < SPARSE_ITERS; k++) {
                const int idx = t + k * THREADS;
                const int el  = idx / NCH;            // local entry 0..9
                const int c   = idx - el * NCH;       // channel 0..84
                const int e   = r * ENTRIES_PER_SPLIT + el;
                const int ok  = (el < ENTRIES_PER_SPLIT) && (e < cnt);
                const int es  = ok ? e : 0;
                const int cell = s_cell[es];
                const float* p;
                if (c < NC)          p = cls_pred + ((size_t)(b * NC + c)) * GG + cell;
                else if (c < NC + 4) p = reg_pred + ((size_t)(b * 4 + (c - NC))) * GG + cell;
                else                 p = obj_pred + (size_t)b * GG + cell;
                vv[k] = __ldg(p);
                ee[k] = es; cc[k] = c; ww[k] = ok ? 1.0f : 0.0f;
            }
            #pragma unroll
            for (int k = 0; k < SPARSE_ITERS; k++) {
                const int   es = ee[k];
                const int   c  = cc[k];
                const float w  = ww[k];
                const float v  = vv[k];
                if (c < NC) {
                    float tt = ((s_bits[es][c >> 5] >> (c & 31)) & 1u) ? 1.0f : 0.0f;
                    a4 += w * (sp(v) - v * tt);
                } else if (c < NC + 4) {
                    float d = v - s_reg[es][c - NC];
                    a3 += w * d * d;
                } else {
                    a1 += w * v;
                    a2 += w * sp(v);
                }
            }
        }

        float w1 = warp_sum(a1), w2 = warp_sum(a2), w3 = warp_sum(a3), w4 = warp_sum(a4);
        if (lane == 0) {
            swsum[wid][0] = w1; swsum[wid][1] = w2;
            swsum[wid][2] = w3; swsum[wid][3] = w4;
        }
        __syncthreads();
        if (t == 0) {
            double r1 = 0.0, r2 = 0.0, r3 = 0.0, r4 = 0.0;
            #pragma unroll
            for (int i = 0; i < NWARPS; i++) {
                r1 += (double)swsum[i][0]; r2 += (double)swsum[i][1];
                r3 += (double)swsum[i][2]; r4 += (double)swsum[i][3];
            }
            if (r1 != 0.0) atomicAdd(&g_acc[1], r1);
            if (r2 != 0.0) atomicAdd(&g_acc[2], r2);
            if (r3 != 0.0) atomicAdd(&g_acc[3], r3);
            if (r4 != 0.0) atomicAdd(&g_acc[4], r4);
        }
    }

    // ---------------- finalize: last block computes outputs & resets state ---
    if (t == 0) {
        __threadfence();
        int old = atomicAdd(&g_done, 1);
        is_last = (old == GRID_BLOCKS - 1);
    }
    __syncthreads();

    if (is_last && t == 0) {
        const double LN2 = 0.6931471805599453;
        double S1   = atomic_read_reset(&g_acc[0]);
        double so   = atomic_read_reset(&g_acc[1]);
        double ssp  = atomic_read_reset(&g_acc[2]);
        double crd  = atomic_read_reset(&g_acc[3]);
        double clsS = atomic_read_reset(&g_acc[4]);
        double M    = (double)atomicExch(&g_Mtot, 0);
        atomicExch(&g_done, 0);

        double obj_loss   = S1 - so;
        double noobj_loss = 0.5 * (S1 - ssp + M * LN2);
        double coord_loss = 5.0 * crd;
        double cls_loss   = LN2 * (double)NC * ((double)OBJ_TOTAL - M) + clsS;
        double total      = obj_loss + noobj_loss + coord_loss + cls_loss;

        out[0] = (float)(total      / (double)NB);
        out[1] = (float)(obj_loss   / (double)NB);
        out[2] = (float)(noobj_loss / (double)NB);
        out[3] = (float)(coord_loss / (double)NB);
        out[4] = (float)(cls_loss   / (double)NB);
    }
}

extern "C" void kernel_launch(void* const* d_in, const int* in_sizes, int n_in,
                              void* d_out, int out_size) {
    const float* cls_pred   = (const float*)d_in[0];
    const float* reg_pred   = (const float*)d_in[1];
    const float* obj_pred   = (const float*)d_in[2];
    const int*   target_cls = (const int*)  d_in[3];
    const float* target_box = (const float*)d_in[4];
    float* out = (float*)d_out;

    yolo_loss_fused_kernel<<<GRID_BLOCKS, THREADS>>>(
        cls_pred, reg_pred, obj_pred, target_cls, target_box, out);
}